// round 7
// baseline (speedup 1.0000x reference)
#include <cuda_runtime.h>
#include <cuda_bf16.h>
#include <math_constants.h>

#define THREADS 256
#define D 4096
#define V4T (D / 4 / THREADS)   // 4 float4 per thread
#define EPT (V4T * 4)           // 16 floats per thread
#define NW (THREADS / 32)       // 8 warps
#define CANDCAP 64
#define SORTN 32
#define NCTAS 912               // 6 CTAs/SM on 152-SM GB300 (grid-stride: any SM count OK)

__device__ __forceinline__ void cp_async16(unsigned saddr, const void* gaddr) {
    asm volatile("cp.async.cg.shared.global [%0], [%1], 16;" :: "r"(saddr), "l"(gaddr) : "memory");
}
__device__ __forceinline__ void cp_commit() { asm volatile("cp.async.commit_group;" ::: "memory"); }
__device__ __forceinline__ void cp_wait0()  { asm volatile("cp.async.wait_group 0;" ::: "memory"); }

__global__ __launch_bounds__(THREADS, 6)
void sparsemax_kernel(const float* __restrict__ in, float* __restrict__ out, int n_rows)
{
    __shared__ float sz[D];            // 16KB landing pad for cp.async
    __shared__ float red[2][NW];       // parity-indexed warp maxes (cross-row race-free)
    __shared__ int   s_cnt[2];         // parity-indexed candidate counters
    __shared__ float cand[CANDCAP];
    __shared__ float fred[NW], fredb[NW];  // fallback-only reductions
    __shared__ float s_tau;
    __shared__ int   s_done;

    const int t    = threadIdx.x;
    const int lane = t & 31;
    const int wid  = t >> 5;
    const unsigned FULL = 0xFFFFFFFFu;
    const unsigned sbase = (unsigned)__cvta_generic_to_shared(sz);
    const int G = gridDim.x;

    if (t == 0) { s_cnt[0] = 0; s_cnt[1] = 0; }   // visible at first B0

    long long row = blockIdx.x;
    if (row < n_rows) {
        const float* rin = in + row * (long long)D;
#pragma unroll
        for (int i = 0; i < V4T; ++i)
            cp_async16(sbase + (unsigned)(t + i * THREADS) * 16u, rin + (t + i * THREADS) * 4);
    }
    cp_commit();

    int p = 0;
    for (; row < n_rows; row += G, p ^= 1) {
        cp_wait0();   // current row landed (per-thread; we read only our own slice)

        // ---- own smem slice -> registers, tracking quad maxes
        float z[EPT];
        float qm[V4T];
        const float4* sv = reinterpret_cast<const float4*>(sz);
#pragma unroll
        for (int i = 0; i < V4T; ++i) {
            float4 v = sv[t + i * THREADS];
            z[4*i+0] = v.x; z[4*i+1] = v.y; z[4*i+2] = v.z; z[4*i+3] = v.w;
            qm[i] = fmaxf(fmaxf(v.x, v.y), fmaxf(v.z, v.w));
        }

        // ---- prefetch next row into the SAME buffer (own slice already consumed);
        // overlaps the entire compute phase below.
        {
            long long nxt = row + G;
            if (nxt < n_rows) {
                const float* rin = in + nxt * (long long)D;
#pragma unroll
                for (int i = 0; i < V4T; ++i)
                    cp_async16(sbase + (unsigned)(t + i * THREADS) * 16u, rin + (t + i * THREADS) * 4);
            }
            cp_commit();
        }

        // ---- warp max -> block max
        float m = fmaxf(fmaxf(qm[0], qm[1]), fmaxf(qm[2], qm[3]));
#pragma unroll
        for (int off = 16; off >= 1; off >>= 1)
            m = fmaxf(m, __shfl_xor_sync(FULL, m, off));
        if (lane == 0) red[p][wid] = m;
        __syncthreads();                          // B0

        float zmax = red[p][0];
#pragma unroll
        for (int w = 1; w < NW; ++w) zmax = fmaxf(zmax, red[p][w]);
        const float lo = zmax - 1.0f;             // tau in [lo, zmax)

        if (t == 0) s_cnt[p ^ 1] = 0;             // reset for NEXT row (safe: post-B0)

        // ---- compaction from registers with quad-skip; REDUX-aggregated atomics
#pragma unroll
        for (int q = 0; q < V4T; ++q) {
            if (__any_sync(FULL, qm[q] > lo)) {
#pragma unroll
                for (int e = 0; e < 4; ++e) {
                    float val = z[4*q + e];
                    if (val > lo) {
                        int pos = atomicAdd(&s_cnt[p], 1);
                        if (pos < CANDCAP) cand[pos] = val;
                    }
                }
            }
        }
        __syncthreads();                          // B1
        const int cnt = s_cnt[p];

        float tau;
        if (cnt <= SORTN) {
            // ---- exact closed-form solve, redundantly in every warp
            float v = (lane < cnt) ? cand[lane] : -CUDART_INF_F;
#pragma unroll
            for (int k = 2; k <= 32; k <<= 1) {
#pragma unroll
                for (int j = k >> 1; j > 0; j >>= 1) {
                    float w = __shfl_xor_sync(FULL, v, j);
                    bool lower   = ((lane & j) == 0);
                    bool descBlk = ((lane & k) == 0);
                    v = (lower == descBlk) ? fmaxf(v, w) : fminf(v, w);
                }
            }
            float csum = v;
#pragma unroll
            for (int off = 1; off < 32; off <<= 1) {
                float u = __shfl_up_sync(FULL, csum, off);
                if (lane >= off) csum += u;
            }
            float r1 = (float)(lane + 1);
            bool cond = (lane < cnt) && (1.0f + r1 * v > csum);
            unsigned msk = __ballot_sync(FULL, cond);
            int kidx = 31 - __clz(msk);
            float csk = __shfl_sync(FULL, csum, kidx);
            tau = (csk - 1.0f) / (float)(kidx + 1);
        } else {
            // ---- fallback for arbitrary data: block-wide Newton over registers
            if (t == 0) s_tau = lo;
            __syncthreads();
            float tloc = s_tau;
            for (int it = 0; it < 48; ++it) {
                float s = 0.0f, k = 0.0f;
#pragma unroll
                for (int i = 0; i < EPT; ++i) {
                    float d = z[i] - tloc;
                    if (d > 0.0f) { s += d; k += 1.0f; }
                }
#pragma unroll
                for (int off = 16; off >= 1; off >>= 1) {
                    s += __shfl_xor_sync(FULL, s, off);
                    k += __shfl_xor_sync(FULL, k, off);
                }
                if (lane == 0) { fred[wid] = s; fredb[wid] = k; }
                __syncthreads();
                if (t == 0) {
                    float S = 0.0f, K = 0.0f;
#pragma unroll
                    for (int w = 0; w < NW; ++w) { S += fred[w]; K += fredb[w]; }
                    float delta = (S - 1.0f) / K;
                    s_tau  = tloc + delta;
                    s_done = (delta < 1e-7f);
                }
                __syncthreads();
                tloc = s_tau;
                if (s_done) break;
            }
            tau = s_tau;
        }

        // ---- epilogue: out = max(z - tau, 0), streaming stores
        float4* rout = reinterpret_cast<float4*>(out + row * (long long)D);
#pragma unroll
        for (int i = 0; i < V4T; ++i) {
            float4 o;
            o.x = fmaxf(z[4*i+0] - tau, 0.0f);
            o.y = fmaxf(z[4*i+1] - tau, 0.0f);
            o.z = fmaxf(z[4*i+2] - tau, 0.0f);
            o.w = fmaxf(z[4*i+3] - tau, 0.0f);
            __stcs(rout + t + i * THREADS, o);
        }
    }
}

extern "C" void kernel_launch(void* const* d_in, const int* in_sizes, int n_in,
                              void* d_out, int out_size)
{
    const float* in  = (const float*)d_in[0];
    float*       out = (float*)d_out;
    const int n_rows = in_sizes[0] / D;   // 16384
    sparsemax_kernel<<<NCTAS, THREADS>>>(in, out, n_rows);
}

// round 8
// speedup vs baseline: 1.2161x; 1.2161x over previous
#include <cuda_runtime.h>
#include <cuda_bf16.h>
#include <math_constants.h>

#define THREADS 256
#define D 4096
#define V4T (D / 4 / THREADS)   // 4 float4 per thread
#define EPT (V4T * 4)           // 16 floats per thread
#define NW (THREADS / 32)       // 8 warps
#define CANDCAP 64
#define SORTN 32

__global__ __launch_bounds__(THREADS, 7)
void sparsemax_kernel(const float* __restrict__ in, float* __restrict__ out)
{
    const long long row = blockIdx.x;
    const float4* __restrict__ rin  = reinterpret_cast<const float4*>(in  + row * (long long)D);
    float4* __restrict__       rout = reinterpret_cast<float4*>      (out + row * (long long)D);

    const int t    = threadIdx.x;
    const int lane = t & 31;
    const int wid  = t >> 5;
    const unsigned FULL = 0xFFFFFFFFu;

    __shared__ float red[NW];
    __shared__ float redb[NW];
    __shared__ float cand[CANDCAP];
    __shared__ int   s_cnt;
    __shared__ float s_tau;
    __shared__ int   s_done;

    if (t == 0) s_cnt = 0;

    // ---- Load 16 elements/thread (4x LDG.128 .cs, coalesced), track thread max
    float z[EPT];
    float tm;
#pragma unroll
    for (int i = 0; i < V4T; ++i) {
        float4 v = __ldcs(rin + t + i * THREADS);
        z[4*i+0] = v.x; z[4*i+1] = v.y; z[4*i+2] = v.z; z[4*i+3] = v.w;
        float q = fmaxf(fmaxf(v.x, v.y), fmaxf(v.z, v.w));
        tm = (i == 0) ? q : fmaxf(tm, q);
    }

    // ---- Warp max -> block max
    float m = tm;
#pragma unroll
    for (int off = 16; off >= 1; off >>= 1)
        m = fmaxf(m, __shfl_xor_sync(FULL, m, off));
    if (lane == 0) red[wid] = m;
    __syncthreads();                       // B0: maxes + s_cnt=0 visible

    float zmax = red[0];
#pragma unroll
    for (int w = 1; w < NW; ++w) zmax = fmaxf(zmax, red[w]);
    const float lo = zmax - 1.0f;          // tau in [lo, zmax): only z > lo matter

    // ---- Compaction with thread-level skip: ~0.3% of threads scan their 16
    if (tm > lo) {
#pragma unroll
        for (int i = 0; i < EPT; ++i) {
            if (z[i] > lo) {
                int pos = atomicAdd(&s_cnt, 1);
                if (pos < CANDCAP) cand[pos] = z[i];
            }
        }
    }
    __syncthreads();                       // B1: candidates visible
    const int cnt = s_cnt;

    float tau;
    if (cnt <= SORTN) {
        // ---- Exact closed-form solve, redundantly in EVERY warp (no 3rd barrier)
        float v = (lane < cnt) ? cand[lane] : -CUDART_INF_F;

        // 32-lane bitonic sort, descending
#pragma unroll
        for (int k = 2; k <= 32; k <<= 1) {
#pragma unroll
            for (int j = k >> 1; j > 0; j >>= 1) {
                float w = __shfl_xor_sync(FULL, v, j);
                bool lower   = ((lane & j) == 0);
                bool descBlk = ((lane & k) == 0);
                v = (lower == descBlk) ? fmaxf(v, w) : fminf(v, w);
            }
        }
        // inclusive prefix sum of sorted-descending values
        float csum = v;
#pragma unroll
        for (int off = 1; off < 32; off <<= 1) {
            float u = __shfl_up_sync(FULL, csum, off);
            if (lane >= off) csum += u;
        }
        // support size: largest j with 1 + (j+1)*v_j > csum_j (lane 0 always true)
        float r = (float)(lane + 1);
        bool cond = (lane < cnt) && (1.0f + r * v > csum);
        unsigned msk = __ballot_sync(FULL, cond);
        int kidx = 31 - __clz(msk);
        float csk = __shfl_sync(FULL, csum, kidx);
        tau = (csk - 1.0f) / (float)(kidx + 1);
    } else {
        // ---- Fallback for arbitrary data: block-wide Newton over registers
        if (t == 0) s_tau = lo;
        __syncthreads();
        float tloc = s_tau;
        for (int it = 0; it < 48; ++it) {
            float s = 0.0f, k = 0.0f;
#pragma unroll
            for (int i = 0; i < EPT; ++i) {
                float d = z[i] - tloc;
                if (d > 0.0f) { s += d; k += 1.0f; }
            }
#pragma unroll
            for (int off = 16; off >= 1; off >>= 1) {
                s += __shfl_xor_sync(FULL, s, off);
                k += __shfl_xor_sync(FULL, k, off);
            }
            if (lane == 0) { red[wid] = s; redb[wid] = k; }
            __syncthreads();
            if (t == 0) {
                float S = 0.0f, K = 0.0f;
#pragma unroll
                for (int w = 0; w < NW; ++w) { S += red[w]; K += redb[w]; }
                float delta = (S - 1.0f) / K;
                s_tau  = tloc + delta;
                s_done = (delta < 1e-7f);
            }
            __syncthreads();
            tloc = s_tau;
            if (s_done) break;
        }
        tau = s_tau;
    }

    // ---- Epilogue: out = max(z - tau, 0), streaming stores
#pragma unroll
    for (int i = 0; i < V4T; ++i) {
        float4 o;
        o.x = fmaxf(z[4*i+0] - tau, 0.0f);
        o.y = fmaxf(z[4*i+1] - tau, 0.0f);
        o.z = fmaxf(z[4*i+2] - tau, 0.0f);
        o.w = fmaxf(z[4*i+3] - tau, 0.0f);
        __stcs(rout + t + i * THREADS, o);
    }
}

extern "C" void kernel_launch(void* const* d_in, const int* in_sizes, int n_in,
                              void* d_out, int out_size)
{
    const float* in  = (const float*)d_in[0];
    float*       out = (float*)d_out;
    const int n_rows = in_sizes[0] / D;   // 16384
    sparsemax_kernel<<<n_rows, THREADS>>>(in, out);
}